// round 2
// baseline (speedup 1.0000x reference)
#include <cuda_runtime.h>
#include <math.h>
#include <stdint.h>

// ---------------- problem constants ----------------
#define BATCH   32768
#define KCODES  4096
#define DLAT    64
#define HIDDEN  1024
#define NHEAD   44      // 40 points + 2 widths + 2 alphas

// output layout (f32, reference return order, flattened+concat)
#define P_OFF    0
#define P_SIZE   (BATCH*40)
#define CP_OFF   (P_OFF + P_SIZE)
#define CP_SIZE  (BATCH*48)
#define W_OFF    (CP_OFF + CP_SIZE)
#define WA_SIZE  (BATCH*2)
#define A_OFF    (W_OFF + WA_SIZE)
#define LOSS_OFF (A_OFF + WA_SIZE)
#define IDX_OFF  (LOSS_OFF + 1)
#define PERP_OFF (IDX_OFF + BATCH)

#define SPAD 4

// ---------------- scratch (__device__ globals; no allocation allowed) ----------------
__device__ float g_h1[BATCH*256];
__device__ float g_h2[BATCH*256];
__device__ float g_z [BATCH*DLAT];
__device__ float g_zq[BATCH*DLAT];
__device__ float g_d1[BATCH*HIDDEN];
__device__ float g_d2[BATCH*HIDDEN];
__device__ float g_ho[BATCH*NHEAD];
__device__ int   g_idx[BATCH];
__device__ float g_counts[KCODES];
__device__ float g_loss;
__device__ float g_enorm[KCODES];
__device__ float g_hw[HIDDEN*NHEAD];
__device__ float g_hb[NHEAD];

// ---------------- activations ----------------
#define ACT_NONE 0
#define ACT_LEAKY 1
#define ACT_SELU 2
#define ACT_HEAD 3

__device__ __forceinline__ float sigmoidf_(float x){ return 1.0f/(1.0f+expf(-x)); }

template<int ACT>
__device__ __forceinline__ float apply_act(float v, int col){
    if (ACT == ACT_LEAKY) return v > 0.0f ? v : 0.2f*v;
    if (ACT == ACT_SELU){
        const float a = 1.6732632423543772f, s = 1.0507009873554805f;
        return v > 0.0f ? s*v : s*a*(expf(v)-1.0f);
    }
    if (ACT == ACT_HEAD){
        if (col < 40) return tanhf(v)*12.0f + 14.0f;
        if (col < 42) return sigmoidf_(v)*2.0f + 1.0f;
        return sigmoidf_(v);
    }
    return v;
}

// ---------------- TF32 split helpers ----------------
__device__ __forceinline__ uint32_t tf32_of(float x){
    uint32_t r; asm("cvt.rna.tf32.f32 %0, %1;" : "=r"(r) : "f"(x)); return r;
}
// returns (hi, lo) both already valid tf32 bit patterns stored as floats
__device__ __forceinline__ float2 split2(float x){
    uint32_t h = tf32_of(x);
    float hf = __uint_as_float(h);
    float lof = __uint_as_float(tf32_of(x - hf));
    return make_float2(hf, lof);
}

// D += A*B, m16n8k8 tf32
__device__ __forceinline__ void mma8(float* c, const uint32_t* a, const uint32_t* b){
    asm volatile(
        "mma.sync.aligned.m16n8k8.row.col.f32.tf32.tf32.f32 "
        "{%0,%1,%2,%3}, {%4,%5,%6,%7}, {%8,%9}, {%0,%1,%2,%3};\n"
        : "+f"(c[0]), "+f"(c[1]), "+f"(c[2]), "+f"(c[3])
        : "r"(a[0]), "r"(a[1]), "r"(a[2]), "r"(a[3]), "r"(b[0]), "r"(b[1]));
}

// ---------------- tensor-core GEMM: C = act(A[M,K] @ W[K,N] + bias) ----------------
// 128x128 tile, BK=16, 8 warps (2 in M x 4 in N), warp tile 64x32,
// split-TF32 (3 mma products) for ~fp32 accuracy.
template<int ACT>
__global__ void __launch_bounds__(256, 2) mma_gemm(
    const float* __restrict__ A, const float* __restrict__ W,
    const float* __restrict__ bias, float* __restrict__ C,
    int M, int N, int K)
{
    __shared__ float2 As[16][128+SPAD];   // [k][m] = (hi, lo)
    __shared__ float2 Bs[16][128+SPAD];   // [k][n] = (hi, lo)

    const int tid  = threadIdx.x;
    const int lane = tid & 31, warp = tid >> 5;
    const int wm = (warp & 1) * 64, wn = (warp >> 1) * 32;
    const int bm = blockIdx.y * 128, bn = blockIdx.x * 128;
    const int g = lane >> 2, tg = lane & 3;

    float acc[4][4][4];
    #pragma unroll
    for (int i = 0; i < 4; i++)
        #pragma unroll
        for (int j = 0; j < 4; j++)
            #pragma unroll
            for (int q = 0; q < 4; q++) acc[i][j][q] = 0.0f;

    const int ar = tid >> 1, ac = (tid & 1) * 8;
    const int br = tid >> 4, bc = (tid & 15) * 4;
    const float* Ap = A + (size_t)(bm + ar) * K + ac;
    const float* Bp = W + (size_t)br * N + bn + bc;

    for (int k0 = 0; k0 < K; k0 += 16){
        float4 av0 = *(const float4*)(Ap + k0);
        float4 av1 = *(const float4*)(Ap + k0 + 4);
        As[ac+0][ar] = split2(av0.x);
        As[ac+1][ar] = split2(av0.y);
        As[ac+2][ar] = split2(av0.z);
        As[ac+3][ar] = split2(av0.w);
        As[ac+4][ar] = split2(av1.x);
        As[ac+5][ar] = split2(av1.y);
        As[ac+6][ar] = split2(av1.z);
        As[ac+7][ar] = split2(av1.w);
        float4 bv0 = *(const float4*)(Bp + (size_t)k0 * N);
        float4 bv1 = *(const float4*)(Bp + (size_t)k0 * N + 64);
        Bs[br][bc+0] = split2(bv0.x);
        Bs[br][bc+1] = split2(bv0.y);
        Bs[br][bc+2] = split2(bv0.z);
        Bs[br][bc+3] = split2(bv0.w);
        Bs[br][bc+64+0] = split2(bv1.x);
        Bs[br][bc+64+1] = split2(bv1.y);
        Bs[br][bc+64+2] = split2(bv1.z);
        Bs[br][bc+64+3] = split2(bv1.w);
        __syncthreads();

        #pragma unroll
        for (int ks = 0; ks < 16; ks += 8){
            uint32_t ah[4][4], al[4][4];
            #pragma unroll
            for (int mt = 0; mt < 4; mt++){
                int m = wm + mt*16 + g;
                float2 v0 = As[ks+tg][m];
                float2 v1 = As[ks+tg][m+8];
                float2 v2 = As[ks+4+tg][m];
                float2 v3 = As[ks+4+tg][m+8];
                ah[mt][0] = __float_as_uint(v0.x);
                ah[mt][1] = __float_as_uint(v1.x);
                ah[mt][2] = __float_as_uint(v2.x);
                ah[mt][3] = __float_as_uint(v3.x);
                al[mt][0] = __float_as_uint(v0.y);
                al[mt][1] = __float_as_uint(v1.y);
                al[mt][2] = __float_as_uint(v2.y);
                al[mt][3] = __float_as_uint(v3.y);
            }
            #pragma unroll
            for (int nt = 0; nt < 4; nt++){
                int n = wn + nt*8 + g;
                float2 w0 = Bs[ks+tg][n];
                float2 w1 = Bs[ks+4+tg][n];
                uint32_t bh[2] = { __float_as_uint(w0.x), __float_as_uint(w1.x) };
                uint32_t bl[2] = { __float_as_uint(w0.y), __float_as_uint(w1.y) };
                #pragma unroll
                for (int mt = 0; mt < 4; mt++) mma8(acc[mt][nt], ah[mt], bh);
                #pragma unroll
                for (int mt = 0; mt < 4; mt++) mma8(acc[mt][nt], al[mt], bh);
                #pragma unroll
                for (int mt = 0; mt < 4; mt++) mma8(acc[mt][nt], ah[mt], bl);
            }
        }
        __syncthreads();
    }

    // epilogue: bias + activation, 64-bit stores
    #pragma unroll
    for (int mt = 0; mt < 4; mt++){
        #pragma unroll
        for (int nt = 0; nt < 4; nt++){
            int row = bm + wm + mt*16 + g;
            int col = bn + wn + nt*8 + 2*tg;
            float bs0 = bias[col], bs1 = bias[col+1];
            float2 o0, o1;
            o0.x = apply_act<ACT>(acc[mt][nt][0] + bs0, col);
            o0.y = apply_act<ACT>(acc[mt][nt][1] + bs1, col+1);
            o1.x = apply_act<ACT>(acc[mt][nt][2] + bs0, col);
            o1.y = apply_act<ACT>(acc[mt][nt][3] + bs1, col+1);
            *(float2*)&C[(size_t)row*N + col]     = o0;
            *(float2*)&C[(size_t)(row+8)*N + col] = o1;
        }
    }
}

// ---------------- small-N SGEMM: 64 rows x N(<=64) cols, BK=16, 4x4 microtile ----------------
template<int ACT>
__global__ void __launch_bounds__(256) sgemm_smallN(
    const float* __restrict__ A, const float* __restrict__ W,
    const float* __restrict__ bias, float* __restrict__ C,
    int M, int N, int K)
{
    __shared__ float As[16][64];
    __shared__ float Bs[16][64];
    const int tid = threadIdx.x;
    const int bm = blockIdx.x * 64;
    const int arow = tid >> 2,  acol = (tid & 3) * 4;
    const int bkr  = tid >> 4,  bcol = (tid & 15) * 4;
    const int ty = tid >> 4, tx = tid & 15;

    float acc[4][4];
    #pragma unroll
    for (int i = 0; i < 4; i++)
        #pragma unroll
        for (int j = 0; j < 4; j++) acc[i][j] = 0.0f;

    for (int k0 = 0; k0 < K; k0 += 16){
        float4 av = *(const float4*)(A + (size_t)(bm + arow) * K + k0 + acol);
        As[acol+0][arow] = av.x;
        As[acol+1][arow] = av.y;
        As[acol+2][arow] = av.z;
        As[acol+3][arow] = av.w;
        float4 bv = make_float4(0.f,0.f,0.f,0.f);
        if (bcol < N) bv = *(const float4*)(W + (size_t)(k0 + bkr) * N + bcol);
        *(float4*)&Bs[bkr][bcol] = bv;
        __syncthreads();
        #pragma unroll
        for (int kk = 0; kk < 16; kk++){
            float a[4], b[4];
            *(float4*)a = *(const float4*)&As[kk][ty*4];
            *(float4*)b = *(const float4*)&Bs[kk][tx*4];
            #pragma unroll
            for (int i = 0; i < 4; i++)
                #pragma unroll
                for (int j = 0; j < 4; j++)
                    acc[i][j] = fmaf(a[i], b[j], acc[i][j]);
        }
        __syncthreads();
    }

    if (tx*4 < N){
        float bsv[4];
        #pragma unroll
        for (int j = 0; j < 4; j++) bsv[j] = bias[tx*4 + j];
        #pragma unroll
        for (int i = 0; i < 4; i++){
            float4 v;
            v.x = apply_act<ACT>(acc[i][0] + bsv[0], tx*4+0);
            v.y = apply_act<ACT>(acc[i][1] + bsv[1], tx*4+1);
            v.z = apply_act<ACT>(acc[i][2] + bsv[2], tx*4+2);
            v.w = apply_act<ACT>(acc[i][3] + bsv[3], tx*4+3);
            *(float4*)(C + (size_t)(bm + ty*4 + i) * N + tx*4) = v;
        }
    }
}

// ---------------- codebook norms ----------------
__global__ void enorm_kernel(const float* __restrict__ emb, float* __restrict__ enorm){
    int k = blockIdx.x * 256 + threadIdx.x;
    if (k >= KCODES) return;
    const float4* e = (const float4*)(emb + (size_t)k * DLAT);
    float s = 0.0f;
    #pragma unroll
    for (int q = 0; q < 16; q++){
        float4 v = e[q];
        s += v.x*v.x + v.y*v.y + v.z*v.z + v.w*v.w;
    }
    enorm[k] = s;
}

// ---------------- VQ argmin via tensor cores: 128 rows x 4096 codes, K=64 ----------------
__global__ void __launch_bounds__(256) vq_argmin_mma(
    const float* __restrict__ z, const float* __restrict__ emb,
    const float* __restrict__ enorm, int* __restrict__ idx_out)
{
    extern __shared__ float2 sm2[];
    float2 (*Zs)[128+SPAD] = (float2 (*)[128+SPAD])sm2;                   // [64][132]
    float2 (*Es)[128+SPAD] = (float2 (*)[128+SPAD])(sm2 + 64*(128+SPAD)); // [64][132]
    float* en = (float*)(sm2 + 2*64*(128+SPAD));                          // [128]

    const int tid  = threadIdx.x;
    const int lane = tid & 31, warp = tid >> 5;
    const int wm = (warp & 1) * 64, wn = (warp >> 1) * 32;
    const int bm = blockIdx.x * 128;
    const int g = lane >> 2, tg = lane & 3;

    // load z tile: [k][m] split form
    const int zr = tid >> 1, zc = (tid & 1) * 32;
    {
        const float* Zp = z + (size_t)(bm + zr) * DLAT + zc;
        #pragma unroll
        for (int q = 0; q < 8; q++){
            float4 v = *(const float4*)(Zp + q*4);
            Zs[zc+q*4+0][zr] = split2(v.x);
            Zs[zc+q*4+1][zr] = split2(v.y);
            Zs[zc+q*4+2][zr] = split2(v.z);
            Zs[zc+q*4+3][zr] = split2(v.w);
        }
    }

    float mv[8]; int mi[8];
    #pragma unroll
    for (int s = 0; s < 8; s++){ mv[s] = INFINITY; mi[s] = 0; }

    for (int c0 = 0; c0 < KCODES; c0 += 128){
        __syncthreads();
        {
            const float* Ep = emb + (size_t)(c0 + zr) * DLAT + zc;
            #pragma unroll
            for (int q = 0; q < 8; q++){
                float4 v = *(const float4*)(Ep + q*4);
                Es[zc+q*4+0][zr] = split2(v.x);
                Es[zc+q*4+1][zr] = split2(v.y);
                Es[zc+q*4+2][zr] = split2(v.z);
                Es[zc+q*4+3][zr] = split2(v.w);
            }
        }
        if (tid < 128) en[tid] = enorm[c0 + tid];
        __syncthreads();

        float acc[4][4][4];
        #pragma unroll
        for (int i = 0; i < 4; i++)
            #pragma unroll
            for (int j = 0; j < 4; j++)
                #pragma unroll
                for (int q = 0; q < 4; q++) acc[i][j][q] = 0.0f;

        #pragma unroll
        for (int ks = 0; ks < DLAT; ks += 8){
            uint32_t ah[4][4], al[4][4];
            #pragma unroll
            for (int mt = 0; mt < 4; mt++){
                int m = wm + mt*16 + g;
                float2 v0 = Zs[ks+tg][m];
                float2 v1 = Zs[ks+tg][m+8];
                float2 v2 = Zs[ks+4+tg][m];
                float2 v3 = Zs[ks+4+tg][m+8];
                ah[mt][0] = __float_as_uint(v0.x);
                ah[mt][1] = __float_as_uint(v1.x);
                ah[mt][2] = __float_as_uint(v2.x);
                ah[mt][3] = __float_as_uint(v3.x);
                al[mt][0] = __float_as_uint(v0.y);
                al[mt][1] = __float_as_uint(v1.y);
                al[mt][2] = __float_as_uint(v2.y);
                al[mt][3] = __float_as_uint(v3.y);
            }
            #pragma unroll
            for (int nt = 0; nt < 4; nt++){
                int n = wn + nt*8 + g;
                float2 w0 = Es[ks+tg][n];
                float2 w1 = Es[ks+4+tg][n];
                uint32_t bh[2] = { __float_as_uint(w0.x), __float_as_uint(w1.x) };
                uint32_t bl[2] = { __float_as_uint(w0.y), __float_as_uint(w1.y) };
                #pragma unroll
                for (int mt = 0; mt < 4; mt++) mma8(acc[mt][nt], ah[mt], bh);
                #pragma unroll
                for (int mt = 0; mt < 4; mt++) mma8(acc[mt][nt], al[mt], bh);
                #pragma unroll
                for (int mt = 0; mt < 4; mt++) mma8(acc[mt][nt], ah[mt], bl);
            }
        }

        // running argmin (ascending code order within thread; strict < keeps first min)
        #pragma unroll
        for (int mt = 0; mt < 4; mt++){
            #pragma unroll
            for (int nt = 0; nt < 4; nt++){
                int nc = wn + nt*8 + 2*tg;
                float e0 = en[nc], e1 = en[nc+1];
                int code = c0 + nc;
                float d00 = e0 - 2.0f*acc[mt][nt][0];
                float d01 = e1 - 2.0f*acc[mt][nt][1];
                float d10 = e0 - 2.0f*acc[mt][nt][2];
                float d11 = e1 - 2.0f*acc[mt][nt][3];
                int s0 = mt*2, s1 = mt*2 + 1;
                if (d00 < mv[s0]){ mv[s0] = d00; mi[s0] = code;   }
                if (d01 < mv[s0]){ mv[s0] = d01; mi[s0] = code+1; }
                if (d10 < mv[s1]){ mv[s1] = d10; mi[s1] = code;   }
                if (d11 < mv[s1]){ mv[s1] = d11; mi[s1] = code+1; }
            }
        }
    }

    __syncthreads();
    float* rv = (float*)Es;           // 16 candidates x 128 rows
    int*   ri = ((int*)Es) + 16*128;
    int cand = (warp >> 1) * 4 + tg;  // 0..15
    #pragma unroll
    for (int s = 0; s < 8; s++){
        int r = wm + (s >> 1)*16 + g + (s & 1)*8;
        rv[cand*128 + r] = mv[s];
        ri[cand*128 + r] = mi[s];
    }
    __syncthreads();
    if (tid < 128){
        float bv = INFINITY; int bi = 0x7fffffff;
        #pragma unroll
        for (int t = 0; t < 16; t++){
            float v = rv[t*128 + tid];
            int c = ri[t*128 + tid];
            if (v < bv || (v == bv && c < bi)){ bv = v; bi = c; }
        }
        idx_out[bm + tid] = bi;
    }
}

// ---------------- gather z_q, idx-as-float, counts, commit-loss partial sums ----------------
__global__ void vq_post(const float* __restrict__ z, const float* __restrict__ emb,
                        const int* __restrict__ idx, float* __restrict__ zq,
                        float* __restrict__ counts, float* __restrict__ loss,
                        float* __restrict__ out_idx)
{
    int b = blockIdx.x * 256 + threadIdx.x;
    int k = idx[b];
    const float4* e  = (const float4*)(emb + (size_t)k * DLAT);
    const float4* zz = (const float4*)(z   + (size_t)b * DLAT);
    float4*       zo = (float4*)(zq + (size_t)b * DLAT);
    float s = 0.0f;
    #pragma unroll
    for (int q = 0; q < 16; q++){
        float4 ev = e[q], zv = zz[q];
        float dx = ev.x - zv.x, dy = ev.y - zv.y, dz = ev.z - zv.z, dw = ev.w - zv.w;
        s += dx*dx + dy*dy + dz*dz + dw*dw;
        zo[q] = ev;
    }
    out_idx[b] = (float)k;
    atomicAdd(&counts[k], 1.0f);

    __shared__ float red[256];
    red[threadIdx.x] = s;
    __syncthreads();
    for (int off = 128; off > 0; off >>= 1){
        if (threadIdx.x < off) red[threadIdx.x] += red[threadIdx.x + off];
        __syncthreads();
    }
    if (threadIdx.x == 0) atomicAdd(loss, red[0]);
}

// ---------------- perplexity + vq_loss scalars ----------------
__global__ void finalize_kernel(const float* __restrict__ counts, const float* __restrict__ loss,
                                float* __restrict__ out)
{
    __shared__ float red[256];
    float s = 0.0f;
    for (int k = threadIdx.x; k < KCODES; k += 256){
        float p = counts[k] * (1.0f / (float)BATCH);
        s += p * logf(p + 1e-10f);
    }
    red[threadIdx.x] = s;
    __syncthreads();
    for (int off = 128; off > 0; off >>= 1){
        if (threadIdx.x < off) red[threadIdx.x] += red[threadIdx.x + off];
        __syncthreads();
    }
    if (threadIdx.x == 0){
        out[PERP_OFF] = expf(-red[0]);
        out[LOSS_OFF] = loss[0] * (0.25f / ((float)BATCH * (float)DLAT));
    }
}

// ---------------- zero counts + loss ----------------
__global__ void zero_kernel(float* __restrict__ counts, float* __restrict__ loss){
    int i = blockIdx.x * 256 + threadIdx.x;
    if (i < KCODES) counts[i] = 0.0f;
    if (i == KCODES) loss[0] = 0.0f;
}

// ---------------- concat head weights [pW|wW|aW] -> [1024,44], biases -> [44] ----------------
__global__ void concat_head(const float* __restrict__ pW, const float* __restrict__ pb,
                            const float* __restrict__ wW, const float* __restrict__ wb,
                            const float* __restrict__ aW, const float* __restrict__ ab,
                            float* __restrict__ hw, float* __restrict__ hb)
{
    int i = blockIdx.x * 256 + threadIdx.x;
    int total = HIDDEN * NHEAD;
    if (i < total){
        int k = i / NHEAD, col = i % NHEAD;
        float v;
        if (col < 40)      v = pW[k*40 + col];
        else if (col < 42) v = wW[k*2 + (col-40)];
        else               v = aW[k*2 + (col-42)];
        hw[i] = v;
    }
    if (i < NHEAD){
        float v;
        if (i < 40)      v = pb[i];
        else if (i < 42) v = wb[i-40];
        else             v = ab[i-42];
        hb[i] = v;
    }
}

// ---------------- pack outputs: points / control_points / widths / alphas ----------------
__global__ void pack_kernel(const float* __restrict__ ho, float* __restrict__ out){
    int gid = blockIdx.x * 256 + threadIdx.x;
    int b = gid / 92, e = gid % 92;
    if (b >= BATCH) return;
    const float* h = ho + (size_t)b * NHEAD;
    if (e < 40){
        out[P_OFF + (size_t)b*40 + e] = h[e];
    } else if (e < 88){
        int e2 = e - 40;
        int c  = e2 & 1;
        int j  = (e2 >> 1) & 3;
        int sg = (e2 >> 3) % 3;
        int p  = e2 / 24;
        out[CP_OFF + (size_t)b*48 + e2] = h[p*20 + (3*sg + j)*2 + c];
    } else if (e < 90){
        int p = e - 88;
        out[W_OFF + (size_t)b*2 + p] = h[40 + p];
    } else {
        int p = e - 90;
        out[A_OFF + (size_t)b*2 + p] = h[42 + p];
    }
}

// ---------------- launch ----------------
extern "C" void kernel_launch(void* const* d_in, const int* in_sizes, int n_in,
                              void* d_out, int out_size)
{
    (void)in_sizes; (void)n_in; (void)out_size;
    const float* x   = (const float*)d_in[0];
    const float* W1  = (const float*)d_in[1];
    const float* b1  = (const float*)d_in[2];
    const float* W2  = (const float*)d_in[3];
    const float* b2  = (const float*)d_in[4];
    const float* W3  = (const float*)d_in[5];
    const float* b3  = (const float*)d_in[6];
    const float* emb = (const float*)d_in[7];
    const float* dW1 = (const float*)d_in[8];
    const float* db1 = (const float*)d_in[9];
    const float* dW2 = (const float*)d_in[10];
    const float* db2 = (const float*)d_in[11];
    const float* pW  = (const float*)d_in[12];
    const float* pb  = (const float*)d_in[13];
    const float* wW  = (const float*)d_in[14];
    const float* wb  = (const float*)d_in[15];
    const float* aW  = (const float*)d_in[16];
    const float* ab  = (const float*)d_in[17];
    float* out = (float*)d_out;

    float *h1, *h2, *z, *zq, *d1, *d2, *ho, *counts, *loss, *enorm, *hw, *hb;
    int* idx;
    cudaGetSymbolAddress((void**)&h1, g_h1);
    cudaGetSymbolAddress((void**)&h2, g_h2);
    cudaGetSymbolAddress((void**)&z,  g_z);
    cudaGetSymbolAddress((void**)&zq, g_zq);
    cudaGetSymbolAddress((void**)&d1, g_d1);
    cudaGetSymbolAddress((void**)&d2, g_d2);
    cudaGetSymbolAddress((void**)&ho, g_ho);
    cudaGetSymbolAddress((void**)&idx, g_idx);
    cudaGetSymbolAddress((void**)&counts, g_counts);
    cudaGetSymbolAddress((void**)&loss, g_loss);
    cudaGetSymbolAddress((void**)&enorm, g_enorm);
    cudaGetSymbolAddress((void**)&hw, g_hw);
    cudaGetSymbolAddress((void**)&hb, g_hb);

    const int VQ_SMEM = (int)(2*64*(128+SPAD)*sizeof(float2) + 128*sizeof(float));
    cudaFuncSetAttribute(vq_argmin_mma, cudaFuncAttributeMaxDynamicSharedMemorySize, VQ_SMEM);

    // init scalars/counts + head-weight concat + codebook norms
    zero_kernel<<<(KCODES + 1 + 255)/256, 256>>>(counts, loss);
    concat_head<<<(HIDDEN*NHEAD + 255)/256, 256>>>(pW, pb, wW, wb, aW, ab, hw, hb);
    enorm_kernel<<<(KCODES + 255)/256, 256>>>(emb, enorm);

    // encoder (tensor cores, split-TF32)
    mma_gemm<ACT_LEAKY><<<dim3(256/128, BATCH/128), 256>>>(x,  W1, b1, h1, BATCH, 256, 784);
    mma_gemm<ACT_LEAKY><<<dim3(256/128, BATCH/128), 256>>>(h1, W2, b2, h2, BATCH, 256, 256);
    sgemm_smallN<ACT_NONE><<<BATCH/64, 256>>>(h2, W3, b3, z, BATCH, DLAT, 256);

    // VQ (tensor cores, split-TF32, fused argmin)
    vq_argmin_mma<<<BATCH/128, 256, VQ_SMEM>>>(z, emb, enorm, idx);
    vq_post<<<BATCH/256, 256>>>(z, emb, idx, zq, counts, loss, out + IDX_OFF);
    finalize_kernel<<<1, 256>>>(counts, loss, out);

    // decoder (tensor cores, split-TF32)
    mma_gemm<ACT_SELU><<<dim3(HIDDEN/128, BATCH/128), 256>>>(zq, dW1, db1, d1, BATCH, HIDDEN, DLAT);
    mma_gemm<ACT_SELU><<<dim3(HIDDEN/128, BATCH/128), 256>>>(d1, dW2, db2, d2, BATCH, HIDDEN, HIDDEN);
    sgemm_smallN<ACT_HEAD><<<BATCH/64, 256>>>(d2, hw, hb, ho, BATCH, NHEAD, HIDDEN);

    // pack outputs
    pack_kernel<<<(BATCH*92 + 255)/256, 256>>>(ho, out);
}

// round 3
// speedup vs baseline: 1.6259x; 1.6259x over previous
#include <cuda_runtime.h>
#include <math.h>
#include <stdint.h>

// ---------------- problem constants ----------------
#define BATCH   32768
#define KCODES  4096
#define DLAT    64
#define HIDDEN  1024
#define NHEAD   44      // 40 points + 2 widths + 2 alphas

// output layout (f32, reference return order, flattened+concat)
#define P_OFF    0
#define P_SIZE   (BATCH*40)
#define CP_OFF   (P_OFF + P_SIZE)
#define CP_SIZE  (BATCH*48)
#define W_OFF    (CP_OFF + CP_SIZE)
#define WA_SIZE  (BATCH*2)
#define A_OFF    (W_OFF + WA_SIZE)
#define LOSS_OFF (A_OFF + WA_SIZE)
#define IDX_OFF  (LOSS_OFF + 1)
#define PERP_OFF (IDX_OFF + BATCH)

#define SPAD 4

// ---------------- scratch (__device__ globals; no allocation allowed) ----------------
__device__ float g_h1[BATCH*256];
__device__ float g_h2[BATCH*256];
__device__ float g_z [BATCH*DLAT];
__device__ float g_zq[BATCH*DLAT];
__device__ float g_d1[BATCH*HIDDEN];
__device__ float g_d2[BATCH*HIDDEN];
__device__ float g_ho[BATCH*NHEAD];
__device__ int   g_idx[BATCH];
__device__ float g_counts[KCODES];
__device__ float g_loss;
__device__ float g_enorm[KCODES];
__device__ float g_hw[HIDDEN*NHEAD];
__device__ float g_hb[NHEAD];

// ---------------- activations ----------------
#define ACT_NONE 0
#define ACT_LEAKY 1
#define ACT_SELU 2
#define ACT_HEAD 3

__device__ __forceinline__ float sigmoidf_(float x){ return 1.0f/(1.0f+expf(-x)); }

template<int ACT>
__device__ __forceinline__ float apply_act(float v, int col){
    if (ACT == ACT_LEAKY) return v > 0.0f ? v : 0.2f*v;
    if (ACT == ACT_SELU){
        const float a = 1.6732632423543772f, s = 1.0507009873554805f;
        return v > 0.0f ? s*v : s*a*(expf(v)-1.0f);
    }
    if (ACT == ACT_HEAD){
        if (col < 40) return tanhf(v)*12.0f + 14.0f;
        if (col < 42) return sigmoidf_(v)*2.0f + 1.0f;
        return sigmoidf_(v);
    }
    return v;
}

// ---------------- TF32 split helpers ----------------
__device__ __forceinline__ uint32_t tf32_of(float x){
    uint32_t r; asm("cvt.rna.tf32.f32 %0, %1;" : "=r"(r) : "f"(x)); return r;
}
// returns (hi, lo) both already valid tf32 bit patterns stored as floats
__device__ __forceinline__ float2 split2(float x){
    uint32_t h = tf32_of(x);
    float hf = __uint_as_float(h);
    float lof = __uint_as_float(tf32_of(x - hf));
    return make_float2(hf, lof);
}

// D += A*B, m16n8k8 tf32
__device__ __forceinline__ void mma8(float* c, const uint32_t* a, const uint32_t* b){
    asm volatile(
        "mma.sync.aligned.m16n8k8.row.col.f32.tf32.tf32.f32 "
        "{%0,%1,%2,%3}, {%4,%5,%6,%7}, {%8,%9}, {%0,%1,%2,%3};\n"
        : "+f"(c[0]), "+f"(c[1]), "+f"(c[2]), "+f"(c[3])
        : "r"(a[0]), "r"(a[1]), "r"(a[2]), "r"(a[3]), "r"(b[0]), "r"(b[1]));
}

// ---------------- cp.async helpers ----------------
__device__ __forceinline__ void cpasync16(void* dst_smem, const void* src){
    uint32_t s = (uint32_t)__cvta_generic_to_shared(dst_smem);
    asm volatile("cp.async.cg.shared.global [%0], [%1], 16;\n" :: "r"(s), "l"(src));
}
__device__ __forceinline__ void cpasync_commit(){ asm volatile("cp.async.commit_group;\n"); }
template<int NN>
__device__ __forceinline__ void cpasync_wait(){ asm volatile("cp.async.wait_group %0;\n" :: "n"(NN)); }

// ============================================================================
// 1x-TF32 GEMM (decoder path): C = act(A[M,K] @ W[K,N] + bias)
// 128x128 tile, BK=16, 8 warps (2Mx4N), cp.async double-buffered.
// Raw fp32 bits fed to tf32 MMA (HW truncation) — fine for decoder accuracy.
// ============================================================================
#define AST 20
#define BST 136
template<int ACT>
__global__ void __launch_bounds__(256, 2) mma_gemm_1x(
    const float* __restrict__ A, const float* __restrict__ W,
    const float* __restrict__ bias, float* __restrict__ C,
    int M, int N, int K)
{
    __shared__ float As[2][128][AST];
    __shared__ float Bs[2][16][BST];

    const int tid  = threadIdx.x;
    const int lane = tid & 31, warp = tid >> 5;
    const int wm = (warp & 1) * 64, wn = (warp >> 1) * 32;
    const int bm = blockIdx.y * 128, bn = blockIdx.x * 128;
    const int g = lane >> 2, tg = lane & 3;

    float acc[4][4][4];
    #pragma unroll
    for (int i = 0; i < 4; i++)
        #pragma unroll
        for (int j = 0; j < 4; j++)
            #pragma unroll
            for (int q = 0; q < 4; q++) acc[i][j][q] = 0.0f;

    const int ar = tid >> 1, ac = (tid & 1) * 8;
    const int br = tid >> 4, bc = (tid & 15) * 8;
    const float* Ap = A + (size_t)(bm + ar) * K + ac;
    const float* Bp = W + (size_t)br * N + bn + bc;

    const int ntiles = K >> 4;

    // copy tile k-index kt into buffer buf
    #define COPY_TILE(kt, buf) do { \
        const float* ap = Ap + (size_t)(kt) * 16; \
        cpasync16(&As[buf][ar][ac],   ap); \
        cpasync16(&As[buf][ar][ac+4], ap + 4); \
        const float* bp = Bp + (size_t)(kt) * 16 * N; \
        cpasync16(&Bs[buf][br][bc],   bp); \
        cpasync16(&Bs[buf][br][bc+4], bp + 4); \
        cpasync_commit(); \
    } while (0)

    COPY_TILE(0, 0);

    for (int i = 0; i < ntiles; i++){
        int buf = i & 1;
        if (i + 1 < ntiles){
            COPY_TILE(i + 1, buf ^ 1);
            cpasync_wait<1>();
        } else {
            cpasync_wait<0>();
        }
        __syncthreads();

        #pragma unroll
        for (int ks = 0; ks < 16; ks += 8){
            uint32_t a[4][4];
            #pragma unroll
            for (int mt = 0; mt < 4; mt++){
                int m = wm + mt*16 + g;
                a[mt][0] = __float_as_uint(As[buf][m  ][ks+tg]);
                a[mt][1] = __float_as_uint(As[buf][m+8][ks+tg]);
                a[mt][2] = __float_as_uint(As[buf][m  ][ks+tg+4]);
                a[mt][3] = __float_as_uint(As[buf][m+8][ks+tg+4]);
            }
            #pragma unroll
            for (int nt = 0; nt < 4; nt++){
                int n = wn + nt*8 + g;
                uint32_t b[2] = { __float_as_uint(Bs[buf][ks+tg  ][n]),
                                  __float_as_uint(Bs[buf][ks+tg+4][n]) };
                #pragma unroll
                for (int mt = 0; mt < 4; mt++) mma8(acc[mt][nt], a[mt], b);
            }
        }
        __syncthreads();
    }
    #undef COPY_TILE

    // epilogue: bias + activation, 64-bit stores
    #pragma unroll
    for (int mt = 0; mt < 4; mt++){
        #pragma unroll
        for (int nt = 0; nt < 4; nt++){
            int row = bm + wm + mt*16 + g;
            int col = bn + wn + nt*8 + 2*tg;
            float bs0 = bias[col], bs1 = bias[col+1];
            float2 o0, o1;
            o0.x = apply_act<ACT>(acc[mt][nt][0] + bs0, col);
            o0.y = apply_act<ACT>(acc[mt][nt][1] + bs1, col+1);
            o1.x = apply_act<ACT>(acc[mt][nt][2] + bs0, col);
            o1.y = apply_act<ACT>(acc[mt][nt][3] + bs1, col+1);
            *(float2*)&C[(size_t)row*N + col]     = o0;
            *(float2*)&C[(size_t)(row+8)*N + col] = o1;
        }
    }
}

// ---------------- tensor-core GEMM (split-TF32, 3 mma products; encoder) ----------------
template<int ACT>
__global__ void __launch_bounds__(256, 2) mma_gemm(
    const float* __restrict__ A, const float* __restrict__ W,
    const float* __restrict__ bias, float* __restrict__ C,
    int M, int N, int K)
{
    __shared__ float2 As[16][128+SPAD];   // [k][m] = (hi, lo)
    __shared__ float2 Bs[16][128+SPAD];   // [k][n] = (hi, lo)

    const int tid  = threadIdx.x;
    const int lane = tid & 31, warp = tid >> 5;
    const int wm = (warp & 1) * 64, wn = (warp >> 1) * 32;
    const int bm = blockIdx.y * 128, bn = blockIdx.x * 128;
    const int g = lane >> 2, tg = lane & 3;

    float acc[4][4][4];
    #pragma unroll
    for (int i = 0; i < 4; i++)
        #pragma unroll
        for (int j = 0; j < 4; j++)
            #pragma unroll
            for (int q = 0; q < 4; q++) acc[i][j][q] = 0.0f;

    const int ar = tid >> 1, ac = (tid & 1) * 8;
    const int br = tid >> 4, bc = (tid & 15) * 4;
    const float* Ap = A + (size_t)(bm + ar) * K + ac;
    const float* Bp = W + (size_t)br * N + bn + bc;

    for (int k0 = 0; k0 < K; k0 += 16){
        float4 av0 = *(const float4*)(Ap + k0);
        float4 av1 = *(const float4*)(Ap + k0 + 4);
        As[ac+0][ar] = split2(av0.x);
        As[ac+1][ar] = split2(av0.y);
        As[ac+2][ar] = split2(av0.z);
        As[ac+3][ar] = split2(av0.w);
        As[ac+4][ar] = split2(av1.x);
        As[ac+5][ar] = split2(av1.y);
        As[ac+6][ar] = split2(av1.z);
        As[ac+7][ar] = split2(av1.w);
        float4 bv0 = *(const float4*)(Bp + (size_t)k0 * N);
        float4 bv1 = *(const float4*)(Bp + (size_t)k0 * N + 64);
        Bs[br][bc+0] = split2(bv0.x);
        Bs[br][bc+1] = split2(bv0.y);
        Bs[br][bc+2] = split2(bv0.z);
        Bs[br][bc+3] = split2(bv0.w);
        Bs[br][bc+64+0] = split2(bv1.x);
        Bs[br][bc+64+1] = split2(bv1.y);
        Bs[br][bc+64+2] = split2(bv1.z);
        Bs[br][bc+64+3] = split2(bv1.w);
        __syncthreads();

        #pragma unroll
        for (int ks = 0; ks < 16; ks += 8){
            uint32_t ah[4][4], al[4][4];
            #pragma unroll
            for (int mt = 0; mt < 4; mt++){
                int m = wm + mt*16 + g;
                float2 v0 = As[ks+tg][m];
                float2 v1 = As[ks+tg][m+8];
                float2 v2 = As[ks+4+tg][m];
                float2 v3 = As[ks+4+tg][m+8];
                ah[mt][0] = __float_as_uint(v0.x);
                ah[mt][1] = __float_as_uint(v1.x);
                ah[mt][2] = __float_as_uint(v2.x);
                ah[mt][3] = __float_as_uint(v3.x);
                al[mt][0] = __float_as_uint(v0.y);
                al[mt][1] = __float_as_uint(v1.y);
                al[mt][2] = __float_as_uint(v2.y);
                al[mt][3] = __float_as_uint(v3.y);
            }
            #pragma unroll
            for (int nt = 0; nt < 4; nt++){
                int n = wn + nt*8 + g;
                float2 w0 = Bs[ks+tg][n];
                float2 w1 = Bs[ks+4+tg][n];
                uint32_t bh[2] = { __float_as_uint(w0.x), __float_as_uint(w1.x) };
                uint32_t bl[2] = { __float_as_uint(w0.y), __float_as_uint(w1.y) };
                #pragma unroll
                for (int mt = 0; mt < 4; mt++) mma8(acc[mt][nt], ah[mt], bh);
                #pragma unroll
                for (int mt = 0; mt < 4; mt++) mma8(acc[mt][nt], al[mt], bh);
                #pragma unroll
                for (int mt = 0; mt < 4; mt++) mma8(acc[mt][nt], ah[mt], bl);
            }
        }
        __syncthreads();
    }

    // epilogue: bias + activation, 64-bit stores
    #pragma unroll
    for (int mt = 0; mt < 4; mt++){
        #pragma unroll
        for (int nt = 0; nt < 4; nt++){
            int row = bm + wm + mt*16 + g;
            int col = bn + wn + nt*8 + 2*tg;
            float bs0 = bias[col], bs1 = bias[col+1];
            float2 o0, o1;
            o0.x = apply_act<ACT>(acc[mt][nt][0] + bs0, col);
            o0.y = apply_act<ACT>(acc[mt][nt][1] + bs1, col+1);
            o1.x = apply_act<ACT>(acc[mt][nt][2] + bs0, col);
            o1.y = apply_act<ACT>(acc[mt][nt][3] + bs1, col+1);
            *(float2*)&C[(size_t)row*N + col]     = o0;
            *(float2*)&C[(size_t)(row+8)*N + col] = o1;
        }
    }
}

// ---------------- small-N SGEMM: 64 rows x N(<=64) cols, BK=16, 4x4 microtile ----------------
template<int ACT>
__global__ void __launch_bounds__(256) sgemm_smallN(
    const float* __restrict__ A, const float* __restrict__ W,
    const float* __restrict__ bias, float* __restrict__ C,
    int M, int N, int K)
{
    __shared__ float As[16][64];
    __shared__ float Bs[16][64];
    const int tid = threadIdx.x;
    const int bm = blockIdx.x * 64;
    const int arow = tid >> 2,  acol = (tid & 3) * 4;
    const int bkr  = tid >> 4,  bcol = (tid & 15) * 4;
    const int ty = tid >> 4, tx = tid & 15;

    float acc[4][4];
    #pragma unroll
    for (int i = 0; i < 4; i++)
        #pragma unroll
        for (int j = 0; j < 4; j++) acc[i][j] = 0.0f;

    for (int k0 = 0; k0 < K; k0 += 16){
        float4 av = *(const float4*)(A + (size_t)(bm + arow) * K + k0 + acol);
        As[acol+0][arow] = av.x;
        As[acol+1][arow] = av.y;
        As[acol+2][arow] = av.z;
        As[acol+3][arow] = av.w;
        float4 bv = make_float4(0.f,0.f,0.f,0.f);
        if (bcol < N) bv = *(const float4*)(W + (size_t)(k0 + bkr) * N + bcol);
        *(float4*)&Bs[bkr][bcol] = bv;
        __syncthreads();
        #pragma unroll
        for (int kk = 0; kk < 16; kk++){
            float a[4], b[4];
            *(float4*)a = *(const float4*)&As[kk][ty*4];
            *(float4*)b = *(const float4*)&Bs[kk][tx*4];
            #pragma unroll
            for (int i = 0; i < 4; i++)
                #pragma unroll
                for (int j = 0; j < 4; j++)
                    acc[i][j] = fmaf(a[i], b[j], acc[i][j]);
        }
        __syncthreads();
    }

    if (tx*4 < N){
        float bsv[4];
        #pragma unroll
        for (int j = 0; j < 4; j++) bsv[j] = bias[tx*4 + j];
        #pragma unroll
        for (int i = 0; i < 4; i++){
            float4 v;
            v.x = apply_act<ACT>(acc[i][0] + bsv[0], tx*4+0);
            v.y = apply_act<ACT>(acc[i][1] + bsv[1], tx*4+1);
            v.z = apply_act<ACT>(acc[i][2] + bsv[2], tx*4+2);
            v.w = apply_act<ACT>(acc[i][3] + bsv[3], tx*4+3);
            *(float4*)(C + (size_t)(bm + ty*4 + i) * N + tx*4) = v;
        }
    }
}

// ---------------- codebook norms ----------------
__global__ void enorm_kernel(const float* __restrict__ emb, float* __restrict__ enorm){
    int k = blockIdx.x * 256 + threadIdx.x;
    if (k >= KCODES) return;
    const float4* e = (const float4*)(emb + (size_t)k * DLAT);
    float s = 0.0f;
    #pragma unroll
    for (int q = 0; q < 16; q++){
        float4 v = e[q];
        s += v.x*v.x + v.y*v.y + v.z*v.z + v.w*v.w;
    }
    enorm[k] = s;
}

// ---------------- VQ argmin via tensor cores: 128 rows x 4096 codes, K=64 ----------------
__global__ void __launch_bounds__(256) vq_argmin_mma(
    const float* __restrict__ z, const float* __restrict__ emb,
    const float* __restrict__ enorm, int* __restrict__ idx_out)
{
    extern __shared__ float2 sm2[];
    float2 (*Zs)[128+SPAD] = (float2 (*)[128+SPAD])sm2;                   // [64][132]
    float2 (*Es)[128+SPAD] = (float2 (*)[128+SPAD])(sm2 + 64*(128+SPAD)); // [64][132]
    float* en = (float*)(sm2 + 2*64*(128+SPAD));                          // [128]

    const int tid  = threadIdx.x;
    const int lane = tid & 31, warp = tid >> 5;
    const int wm = (warp & 1) * 64, wn = (warp >> 1) * 32;
    const int bm = blockIdx.x * 128;
    const int g = lane >> 2, tg = lane & 3;

    // load z tile: [k][m] split form
    const int zr = tid >> 1, zc = (tid & 1) * 32;
    {
        const float* Zp = z + (size_t)(bm + zr) * DLAT + zc;
        #pragma unroll
        for (int q = 0; q < 8; q++){
            float4 v = *(const float4*)(Zp + q*4);
            Zs[zc+q*4+0][zr] = split2(v.x);
            Zs[zc+q*4+1][zr] = split2(v.y);
            Zs[zc+q*4+2][zr] = split2(v.z);
            Zs[zc+q*4+3][zr] = split2(v.w);
        }
    }

    float mv[8]; int mi[8];
    #pragma unroll
    for (int s = 0; s < 8; s++){ mv[s] = INFINITY; mi[s] = 0; }

    for (int c0 = 0; c0 < KCODES; c0 += 128){
        __syncthreads();
        {
            const float* Ep = emb + (size_t)(c0 + zr) * DLAT + zc;
            #pragma unroll
            for (int q = 0; q < 8; q++){
                float4 v = *(const float4*)(Ep + q*4);
                Es[zc+q*4+0][zr] = split2(v.x);
                Es[zc+q*4+1][zr] = split2(v.y);
                Es[zc+q*4+2][zr] = split2(v.z);
                Es[zc+q*4+3][zr] = split2(v.w);
            }
        }
        if (tid < 128) en[tid] = enorm[c0 + tid];
        __syncthreads();

        float acc[4][4][4];
        #pragma unroll
        for (int i = 0; i < 4; i++)
            #pragma unroll
            for (int j = 0; j < 4; j++)
                #pragma unroll
                for (int q = 0; q < 4; q++) acc[i][j][q] = 0.0f;

        #pragma unroll
        for (int ks = 0; ks < DLAT; ks += 8){
            uint32_t ah[4][4], al[4][4];
            #pragma unroll
            for (int mt = 0; mt < 4; mt++){
                int m = wm + mt*16 + g;
                float2 v0 = Zs[ks+tg][m];
                float2 v1 = Zs[ks+tg][m+8];
                float2 v2 = Zs[ks+4+tg][m];
                float2 v3 = Zs[ks+4+tg][m+8];
                ah[mt][0] = __float_as_uint(v0.x);
                ah[mt][1] = __float_as_uint(v1.x);
                ah[mt][2] = __float_as_uint(v2.x);
                ah[mt][3] = __float_as_uint(v3.x);
                al[mt][0] = __float_as_uint(v0.y);
                al[mt][1] = __float_as_uint(v1.y);
                al[mt][2] = __float_as_uint(v2.y);
                al[mt][3] = __float_as_uint(v3.y);
            }
            #pragma unroll
            for (int nt = 0; nt < 4; nt++){
                int n = wn + nt*8 + g;
                float2 w0 = Es[ks+tg][n];
                float2 w1 = Es[ks+4+tg][n];
                uint32_t bh[2] = { __float_as_uint(w0.x), __float_as_uint(w1.x) };
                uint32_t bl[2] = { __float_as_uint(w0.y), __float_as_uint(w1.y) };
                #pragma unroll
                for (int mt = 0; mt < 4; mt++) mma8(acc[mt][nt], ah[mt], bh);
                #pragma unroll
                for (int mt = 0; mt < 4; mt++) mma8(acc[mt][nt], al[mt], bh);
                #pragma unroll
                for (int mt = 0; mt < 4; mt++) mma8(acc[mt][nt], ah[mt], bl);
            }
        }

        // running argmin (ascending code order within thread; strict < keeps first min)
        #pragma unroll
        for (int mt = 0; mt < 4; mt++){
            #pragma unroll
            for (int nt = 0; nt < 4; nt++){
                int nc = wn + nt*8 + 2*tg;
                float e0 = en[nc], e1 = en[nc+1];
                int code = c0 + nc;
                float d00 = e0 - 2.0f*acc[mt][nt][0];
                float d01 = e1 - 2.0f*acc[mt][nt][1];
                float d10 = e0 - 2.0f*acc[mt][nt][2];
                float d11 = e1 - 2.0f*acc[mt][nt][3];
                int s0 = mt*2, s1 = mt*2 + 1;
                if (d00 < mv[s0]){ mv[s0] = d00; mi[s0] = code;   }
                if (d01 < mv[s0]){ mv[s0] = d01; mi[s0] = code+1; }
                if (d10 < mv[s1]){ mv[s1] = d10; mi[s1] = code;   }
                if (d11 < mv[s1]){ mv[s1] = d11; mi[s1] = code+1; }
            }
        }
    }

    __syncthreads();
    float* rv = (float*)Es;           // 16 candidates x 128 rows
    int*   ri = ((int*)Es) + 16*128;
    int cand = (warp >> 1) * 4 + tg;  // 0..15
    #pragma unroll
    for (int s = 0; s < 8; s++){
        int r = wm + (s >> 1)*16 + g + (s & 1)*8;
        rv[cand*128 + r] = mv[s];
        ri[cand*128 + r] = mi[s];
    }
    __syncthreads();
    if (tid < 128){
        float bv = INFINITY; int bi = 0x7fffffff;
        #pragma unroll
        for (int t = 0; t < 16; t++){
            float v = rv[t*128 + tid];
            int c = ri[t*128 + tid];
            if (v < bv || (v == bv && c < bi)){ bv = v; bi = c; }
        }
        idx_out[bm + tid] = bi;
    }
}

// ---------------- gather z_q, idx-as-float, counts, commit-loss partial sums ----------------
__global__ void vq_post(const float* __restrict__ z, const float* __restrict__ emb,
                        const int* __restrict__ idx, float* __restrict__ zq,
                        float* __restrict__ counts, float* __restrict__ loss,
                        float* __restrict__ out_idx)
{
    int b = blockIdx.x * 256 + threadIdx.x;
    int k = idx[b];
    const float4* e  = (const float4*)(emb + (size_t)k * DLAT);
    const float4* zz = (const float4*)(z   + (size_t)b * DLAT);
    float4*       zo = (float4*)(zq + (size_t)b * DLAT);
    float s = 0.0f;
    #pragma unroll
    for (int q = 0; q < 16; q++){
        float4 ev = e[q], zv = zz[q];
        float dx = ev.x - zv.x, dy = ev.y - zv.y, dz = ev.z - zv.z, dw = ev.w - zv.w;
        s += dx*dx + dy*dy + dz*dz + dw*dw;
        zo[q] = ev;
    }
    out_idx[b] = (float)k;
    atomicAdd(&counts[k], 1.0f);

    __shared__ float red[256];
    red[threadIdx.x] = s;
    __syncthreads();
    for (int off = 128; off > 0; off >>= 1){
        if (threadIdx.x < off) red[threadIdx.x] += red[threadIdx.x + off];
        __syncthreads();
    }
    if (threadIdx.x == 0) atomicAdd(loss, red[0]);
}

// ---------------- perplexity + vq_loss scalars ----------------
__global__ void finalize_kernel(const float* __restrict__ counts, const float* __restrict__ loss,
                                float* __restrict__ out)
{
    __shared__ float red[256];
    float s = 0.0f;
    for (int k = threadIdx.x; k < KCODES; k += 256){
        float p = counts[k] * (1.0f / (float)BATCH);
        s += p * logf(p + 1e-10f);
    }
    red[threadIdx.x] = s;
    __syncthreads();
    for (int off = 128; off > 0; off >>= 1){
        if (threadIdx.x < off) red[threadIdx.x] += red[threadIdx.x + off];
        __syncthreads();
    }
    if (threadIdx.x == 0){
        out[PERP_OFF] = expf(-red[0]);
        out[LOSS_OFF] = loss[0] * (0.25f / ((float)BATCH * (float)DLAT));
    }
}

// ---------------- zero counts + loss ----------------
__global__ void zero_kernel(float* __restrict__ counts, float* __restrict__ loss){
    int i = blockIdx.x * 256 + threadIdx.x;
    if (i < KCODES) counts[i] = 0.0f;
    if (i == KCODES) loss[0] = 0.0f;
}

// ---------------- concat head weights [pW|wW|aW] -> [1024,44], biases -> [44] ----------------
__global__ void concat_head(const float* __restrict__ pW, const float* __restrict__ pb,
                            const float* __restrict__ wW, const float* __restrict__ wb,
                            const float* __restrict__ aW, const float* __restrict__ ab,
                            float* __restrict__ hw, float* __restrict__ hb)
{
    int i = blockIdx.x * 256 + threadIdx.x;
    int total = HIDDEN * NHEAD;
    if (i < total){
        int k = i / NHEAD, col = i % NHEAD;
        float v;
        if (col < 40)      v = pW[k*40 + col];
        else if (col < 42) v = wW[k*2 + (col-40)];
        else               v = aW[k*2 + (col-42)];
        hw[i] = v;
    }
    if (i < NHEAD){
        float v;
        if (i < 40)      v = pb[i];
        else if (i < 42) v = wb[i-40];
        else             v = ab[i-42];
        hb[i] = v;
    }
}

// ---------------- pack outputs: points / control_points / widths / alphas ----------------
__global__ void pack_kernel(const float* __restrict__ ho, float* __restrict__ out){
    int gid = blockIdx.x * 256 + threadIdx.x;
    int b = gid / 92, e = gid % 92;
    if (b >= BATCH) return;
    const float* h = ho + (size_t)b * NHEAD;
    if (e < 40){
        out[P_OFF + (size_t)b*40 + e] = h[e];
    } else if (e < 88){
        int e2 = e - 40;
        int c  = e2 & 1;
        int j  = (e2 >> 1) & 3;
        int sg = (e2 >> 3) % 3;
        int p  = e2 / 24;
        out[CP_OFF + (size_t)b*48 + e2] = h[p*20 + (3*sg + j)*2 + c];
    } else if (e < 90){
        int p = e - 88;
        out[W_OFF + (size_t)b*2 + p] = h[40 + p];
    } else {
        int p = e - 90;
        out[A_OFF + (size_t)b*2 + p] = h[42 + p];
    }
}

// ---------------- launch ----------------
extern "C" void kernel_launch(void* const* d_in, const int* in_sizes, int n_in,
                              void* d_out, int out_size)
{
    (void)in_sizes; (void)n_in; (void)out_size;
    const float* x   = (const float*)d_in[0];
    const float* W1  = (const float*)d_in[1];
    const float* b1  = (const float*)d_in[2];
    const float* W2  = (const float*)d_in[3];
    const float* b2  = (const float*)d_in[4];
    const float* W3  = (const float*)d_in[5];
    const float* b3  = (const float*)d_in[6];
    const float* emb = (const float*)d_in[7];
    const float* dW1 = (const float*)d_in[8];
    const float* db1 = (const float*)d_in[9];
    const float* dW2 = (const float*)d_in[10];
    const float* db2 = (const float*)d_in[11];
    const float* pW  = (const float*)d_in[12];
    const float* pb  = (const float*)d_in[13];
    const float* wW  = (const float*)d_in[14];
    const float* wb  = (const float*)d_in[15];
    const float* aW  = (const float*)d_in[16];
    const float* ab  = (const float*)d_in[17];
    float* out = (float*)d_out;

    float *h1, *h2, *z, *zq, *d1, *d2, *ho, *counts, *loss, *enorm, *hw, *hb;
    int* idx;
    cudaGetSymbolAddress((void**)&h1, g_h1);
    cudaGetSymbolAddress((void**)&h2, g_h2);
    cudaGetSymbolAddress((void**)&z,  g_z);
    cudaGetSymbolAddress((void**)&zq, g_zq);
    cudaGetSymbolAddress((void**)&d1, g_d1);
    cudaGetSymbolAddress((void**)&d2, g_d2);
    cudaGetSymbolAddress((void**)&ho, g_ho);
    cudaGetSymbolAddress((void**)&idx, g_idx);
    cudaGetSymbolAddress((void**)&counts, g_counts);
    cudaGetSymbolAddress((void**)&loss, g_loss);
    cudaGetSymbolAddress((void**)&enorm, g_enorm);
    cudaGetSymbolAddress((void**)&hw, g_hw);
    cudaGetSymbolAddress((void**)&hb, g_hb);

    const int VQ_SMEM = (int)(2*64*(128+SPAD)*sizeof(float2) + 128*sizeof(float));
    cudaFuncSetAttribute(vq_argmin_mma, cudaFuncAttributeMaxDynamicSharedMemorySize, VQ_SMEM);

    // init scalars/counts + head-weight concat + codebook norms
    zero_kernel<<<(KCODES + 1 + 255)/256, 256>>>(counts, loss);
    concat_head<<<(HIDDEN*NHEAD + 255)/256, 256>>>(pW, pb, wW, wb, aW, ab, hw, hb);
    enorm_kernel<<<(KCODES + 255)/256, 256>>>(emb, enorm);

    // encoder (tensor cores, split-TF32 for argmin safety)
    mma_gemm<ACT_LEAKY><<<dim3(256/128, BATCH/128), 256>>>(x,  W1, b1, h1, BATCH, 256, 784);
    mma_gemm<ACT_LEAKY><<<dim3(256/128, BATCH/128), 256>>>(h1, W2, b2, h2, BATCH, 256, 256);
    sgemm_smallN<ACT_NONE><<<BATCH/64, 256>>>(h2, W3, b3, z, BATCH, DLAT, 256);

    // VQ (tensor cores, split-TF32, fused argmin)
    vq_argmin_mma<<<BATCH/128, 256, VQ_SMEM>>>(z, emb, enorm, idx);
    vq_post<<<BATCH/256, 256>>>(z, emb, idx, zq, counts, loss, out + IDX_OFF);
    finalize_kernel<<<1, 256>>>(counts, loss, out);

    // decoder (tensor cores, 1x TF32 + cp.async pipeline; errors diluted by idx norm)
    mma_gemm_1x<ACT_SELU><<<dim3(HIDDEN/128, BATCH/128), 256>>>(zq, dW1, db1, d1, BATCH, HIDDEN, DLAT);
    mma_gemm_1x<ACT_SELU><<<dim3(HIDDEN/128, BATCH/128), 256>>>(d1, dW2, db2, d2, BATCH, HIDDEN, HIDDEN);
    sgemm_smallN<ACT_HEAD><<<BATCH/64, 256>>>(d2, hw, hb, ho, BATCH, NHEAD, HIDDEN);

    // pack outputs
    pack_kernel<<<(BATCH*92 + 255)/256, 256>>>(ho, out);
}